// round 13
// baseline (speedup 1.0000x reference)
#include <cuda_runtime.h>
#include <cuda_bf16.h>
#include <cstdint>
#include <math.h>

#define TSTEPS 512
#define BATCH  64
#define NIN    512
#define NH     1024
#define NBLK   128

// ============================ global scratch ================================
__device__ float g_X[(size_t)3 * TSTEPS * BATCH * NH];   // input projections
// A-operand planes, frag order per half: (kf*2+mf)*32+lane, kf 0..63, mf 0..1
__device__ uint4 g_hhf[2][2][4096], g_hlf[2][2][4096];   // h planes [parity][half]
__device__ uint4 g_rhhf[2][4096], g_rhlf[2][4096];       // r*h planes [half]
__device__ int g_fh[128], g_frh[128];                    // flags [j + 64*half]

// ============================ helpers =======================================
__device__ __forceinline__ uint32_t bfpack(float x, float y) {
    __nv_bfloat162 t = __floats2bfloat162_rn(x, y);
    return *(uint32_t*)&t;
}
__device__ __forceinline__ void splitp(float x, float y, uint32_t& hi, uint32_t& lo) {
    float hx = __bfloat162float(__float2bfloat16(x));
    float hy = __bfloat162float(__float2bfloat16(y));
    hi = bfpack(hx, hy);
    lo = bfpack(x - hx, y - hy);
}
__device__ __forceinline__ void mma16816(float* c, const uint32_t* a, const uint32_t* b) {
    asm volatile("mma.sync.aligned.m16n8k16.row.col.f32.bf16.bf16.f32 "
        "{%0,%1,%2,%3},{%4,%5,%6,%7},{%8,%9},{%0,%1,%2,%3};"
        : "+f"(c[0]), "+f"(c[1]), "+f"(c[2]), "+f"(c[3])
        : "r"(a[0]), "r"(a[1]), "r"(a[2]), "r"(a[3]), "r"(b[0]), "r"(b[1]));
}
__device__ __forceinline__ int ld_acq(const int* p) {
    int v;
    asm volatile("ld.acquire.gpu.global.s32 %0, [%1];" : "=r"(v) : "l"(p) : "memory");
    return v;
}
__device__ __forceinline__ void st_rel(int* p, int v) {
    asm volatile("st.release.gpu.global.s32 [%0], %1;" :: "l"(p), "r"(v) : "memory");
}
// single-warp polling of 64 flags (warp 0), block released by syncthreads
__device__ __forceinline__ void block_wait64(const int* flags, int target) {
    if (threadIdx.x < 32) {
        const int* p0 = flags + threadIdx.x;
        const int* p1 = flags + 32 + threadIdx.x;
        while (!__all_sync(0xFFFFFFFFu,
                           (ld_acq(p0) >= target) && (ld_acq(p1) >= target)))
            __nanosleep(60);
    }
    __syncthreads();
}

// =================== init: reset flags each launch ==========================
__global__ void init_misc_kernel() {
    int i = threadIdx.x;
    if (i < 128) { g_fh[i] = -1; g_frh[i] = -1; }
}

// ======================= phase A: input projections =========================
#define PA_AH 0
#define PA_AL 32768
#define PA_WH 65536
#define PA_WL 98304
#define PA_SMEM 131072

__global__ void __launch_bounds__(256) input_proj_kernel(
    const float* __restrict__ input,
    const float* __restrict__ Wiz, const float* __restrict__ Wir,
    const float* __restrict__ Wih)
{
    extern __shared__ char sm[];
    uint4* Ah = (uint4*)(sm + PA_AH);
    uint4* Al = (uint4*)(sm + PA_AL);
    uint2* Wh = (uint2*)(sm + PA_WH);
    uint2* Wl = (uint2*)(sm + PA_WL);
    const int tid = threadIdx.x, wid = tid >> 5, lane = tid & 31;
    const int ntile = blockIdx.x % 24, mtile = blockIdx.x / 24;
    const int gate = ntile >> 3, n0g = (ntile & 7) * 128, m0 = mtile * 128;
    const float* W = (gate == 0) ? Wiz : ((gate == 1) ? Wir : Wih);
    const int mg = wid & 3, ng = wid >> 2;

    float c[2][8][4];
#pragma unroll
    for (int i = 0; i < 2; i++)
#pragma unroll
        for (int j = 0; j < 8; j++)
#pragma unroll
            for (int k = 0; k < 4; k++) c[i][j][k] = 0.0f;

    for (int ch = 0; ch < 4; ch++) {
        const int k0 = ch * 128;
        __syncthreads();
#pragma unroll
        for (int it = 0; it < 8; it++) {
            int idx = tid + (it << 8);
            int frag = idx >> 5, l = idx & 31;
            int kf = frag >> 3, mf = frag & 7;
            int r = l >> 2, c2 = (l & 3) * 2;
            const float* src = input + (size_t)(m0 + mf * 16 + r) * NIN + k0 + kf * 16 + c2;
            float2 p0 = *(const float2*)(src);
            float2 p1 = *(const float2*)(src + 8 * NIN);
            float2 p2 = *(const float2*)(src + 8);
            float2 p3 = *(const float2*)(src + 8 * NIN + 8);
            uint32_t h0, h1, h2, h3, lo0, lo1, lo2, lo3;
            splitp(p0.x, p0.y, h0, lo0); splitp(p1.x, p1.y, h1, lo1);
            splitp(p2.x, p2.y, h2, lo2); splitp(p3.x, p3.y, h3, lo3);
            Ah[frag * 32 + l] = make_uint4(h0, h1, h2, h3);
            Al[frag * 32 + l] = make_uint4(lo0, lo1, lo2, lo3);
        }
#pragma unroll
        for (int it = 0; it < 16; it++) {
            int idx = tid + (it << 8);
            int frag = idx >> 5, l = idx & 31;
            int kf = frag >> 4, nf = frag & 15;
            int n = nf * 8 + (l >> 2), k = kf * 16 + (l & 3) * 2;
            const float* src = W + (size_t)(n0g + n) * NIN + k0 + k;
            float2 q0 = *(const float2*)src;
            float2 q1 = *(const float2*)(src + 8);
            uint32_t h0, h1, lo0, lo1;
            splitp(q0.x, q0.y, h0, lo0); splitp(q1.x, q1.y, h1, lo1);
            Wh[frag * 32 + l] = make_uint2(h0, h1);
            Wl[frag * 32 + l] = make_uint2(lo0, lo1);
        }
        __syncthreads();
#pragma unroll 2
        for (int s = 0; s < 8; s++) {
            uint4 ah[2], al[2];
            uint2 bh[8], bl[8];
            ah[0] = Ah[(s * 8 + mg * 2 + 0) * 32 + lane];
            ah[1] = Ah[(s * 8 + mg * 2 + 1) * 32 + lane];
            al[0] = Al[(s * 8 + mg * 2 + 0) * 32 + lane];
            al[1] = Al[(s * 8 + mg * 2 + 1) * 32 + lane];
#pragma unroll
            for (int nf = 0; nf < 8; nf++) {
                bh[nf] = Wh[(s * 16 + ng * 8 + nf) * 32 + lane];
                bl[nf] = Wl[(s * 16 + ng * 8 + nf) * 32 + lane];
            }
#pragma unroll
            for (int mf = 0; mf < 2; mf++)
#pragma unroll
                for (int nf = 0; nf < 8; nf++) {
                    mma16816(c[mf][nf], &ah[mf].x, &bh[nf].x);
                    mma16816(c[mf][nf], &al[mf].x, &bh[nf].x);
                    mma16816(c[mf][nf], &ah[mf].x, &bl[nf].x);
                }
        }
    }
    const int r = lane >> 2, c2 = (lane & 3) * 2;
#pragma unroll
    for (int mf = 0; mf < 2; mf++)
#pragma unroll
        for (int nf = 0; nf < 8; nf++) {
            size_t row = (size_t)(m0 + (mg * 2 + mf) * 16 + r);
            size_t base = ((size_t)gate * TSTEPS * BATCH + row) * NH
                        + n0g + (ng * 8 + nf) * 8 + c2;
            *(float2*)(g_X + base) = make_float2(c[mf][nf][0], c[mf][nf][1]);
            *(float2*)(g_X + base + (size_t)8 * NH) = make_float2(c[mf][nf][2], c[mf][nf][3]);
        }
}

// ======================= phase B: persistent GRU ============================
// 128 blocks = 2 independent chains (half = batch rows 0-31 / 32-63).
// Block (half, j): 32 rows x 16 cols. 2 hops/step. Direct frag epilogue.
#define W_ZH 0
#define W_ZL 32768
#define W_RH 65536
#define W_RL 98304
#define W_CH 131072
#define W_CL 163840
#define PB_SCRZ 196608  // float[4][32][20] = 10240
#define PB_SCRR 206848  // float[4][32][20] = 10240
#define PB_BIA  217088  // float[48]: z|r|c
#define PB_SLEN 217280  // int[32]
#define PB_SMEM 217600

// pack full-K W slice (16 cols x 1024) into 128 B-frag-order split frags
__device__ __forceinline__ void packW(const float* __restrict__ W, int gn0,
                                      uint2* __restrict__ Dh, uint2* __restrict__ Dl,
                                      int tid)
{
#pragma unroll 4
    for (int it = 0; it < 16; it++) {
        int idx = tid + (it << 8);
        int frag = idx >> 5, l = idx & 31;
        int kf = frag >> 1, nf = frag & 1;
        int n = nf * 8 + (l >> 2), k = kf * 16 + (l & 3) * 2;
        const float* src = W + (size_t)(gn0 + n) * NH + k;
        float2 q0 = *(const float2*)src;
        float2 q1 = *(const float2*)(src + 8);
        uint32_t h0, h1, lo0, lo1;
        splitp(q0.x, q0.y, h0, lo0); splitp(q1.x, q1.y, h1, lo1);
        Dh[frag * 32 + l] = make_uint2(h0, h1);
        Dl[frag * 32 + l] = make_uint2(lo0, lo1);
    }
}

// fused z+r gemm, depth-4 A prefetch. 8 warps: mf=wid&1, kg=wid>>1.
__device__ __forceinline__ void gemm_zr(const uint4* __restrict__ Aph,
                                        const uint4* __restrict__ Apl,
                                        const uint2* __restrict__ Wzh, const uint2* __restrict__ Wzl,
                                        const uint2* __restrict__ Wrh, const uint2* __restrict__ Wrl,
                                        float* __restrict__ scrz, float* __restrict__ scrr,
                                        int wid, int lane)
{
    const int mf = wid & 1, kg = wid >> 1;
    const int kf0 = kg * 16;
    float cz[2][4], cr[2][4];
#pragma unroll
    for (int j = 0; j < 2; j++)
#pragma unroll
        for (int k = 0; k < 4; k++) { cz[j][k] = 0.0f; cr[j][k] = 0.0f; }

    uint4 ah[4], al[4];
    uint2 bzh[2][2], bzl[2][2], brh[2][2], brl[2][2];
#pragma unroll
    for (int p = 0; p < 3; p++) {
        int af = ((kf0 + p) * 2 + mf) * 32 + lane;
        ah[p] = Aph[af]; al[p] = Apl[af];
    }
    {
        int wf = (kf0 * 2) * 32 + lane;
        bzh[0][0] = Wzh[wf]; bzh[0][1] = Wzh[wf + 32];
        bzl[0][0] = Wzl[wf]; bzl[0][1] = Wzl[wf + 32];
        brh[0][0] = Wrh[wf]; brh[0][1] = Wrh[wf + 32];
        brl[0][0] = Wrl[wf]; brl[0][1] = Wrl[wf + 32];
    }
#pragma unroll
    for (int s = 0; s < 16; s++) {
        const int cur = s & 3, wcur = s & 1, wnxt = wcur ^ 1;
        if (s + 3 < 16) {
            int af = ((kf0 + s + 3) * 2 + mf) * 32 + lane;
            ah[(s + 3) & 3] = Aph[af]; al[(s + 3) & 3] = Apl[af];
        }
        if (s < 15) {
            int wf = ((kf0 + s + 1) * 2) * 32 + lane;
            bzh[wnxt][0] = Wzh[wf]; bzh[wnxt][1] = Wzh[wf + 32];
            bzl[wnxt][0] = Wzl[wf]; bzl[wnxt][1] = Wzl[wf + 32];
            brh[wnxt][0] = Wrh[wf]; brh[wnxt][1] = Wrh[wf + 32];
            brl[wnxt][0] = Wrl[wf]; brl[wnxt][1] = Wrl[wf + 32];
        }
#pragma unroll
        for (int nf = 0; nf < 2; nf++) {
            mma16816(cz[nf], &ah[cur].x, &bzh[wcur][nf].x);
            mma16816(cz[nf], &al[cur].x, &bzh[wcur][nf].x);
            mma16816(cz[nf], &ah[cur].x, &bzl[wcur][nf].x);
            mma16816(cr[nf], &ah[cur].x, &brh[wcur][nf].x);
            mma16816(cr[nf], &al[cur].x, &brh[wcur][nf].x);
            mma16816(cr[nf], &ah[cur].x, &brl[wcur][nf].x);
        }
    }
    const int r = lane >> 2, c2 = (lane & 3) * 2;
#pragma unroll
    for (int nf = 0; nf < 2; nf++) {
        int off = kg * 640 + (mf * 16 + r) * 20 + nf * 8 + c2;
        *(float2*)(scrz + off) = make_float2(cz[nf][0], cz[nf][1]);
        *(float2*)(scrz + off + 8 * 20) = make_float2(cz[nf][2], cz[nf][3]);
        *(float2*)(scrr + off) = make_float2(cr[nf][0], cr[nf][1]);
        *(float2*)(scrr + off + 8 * 20) = make_float2(cr[nf][2], cr[nf][3]);
    }
}

// candidate gemm, depth-4 A prefetch
__device__ __forceinline__ void gemm_c(const uint4* __restrict__ Aph,
                                       const uint4* __restrict__ Apl,
                                       const uint2* __restrict__ Wh,
                                       const uint2* __restrict__ Wl,
                                       float* __restrict__ scr,
                                       int wid, int lane)
{
    const int mf = wid & 1, kg = wid >> 1;
    const int kf0 = kg * 16;
    float c[2][4];
#pragma unroll
    for (int j = 0; j < 2; j++)
#pragma unroll
        for (int k = 0; k < 4; k++) c[j][k] = 0.0f;

    uint4 ah[4], al[4];
    uint2 bh[2][2], bl[2][2];
#pragma unroll
    for (int p = 0; p < 3; p++) {
        int af = ((kf0 + p) * 2 + mf) * 32 + lane;
        ah[p] = Aph[af]; al[p] = Apl[af];
    }
    {
        int wf = (kf0 * 2) * 32 + lane;
        bh[0][0] = Wh[wf]; bh[0][1] = Wh[wf + 32];
        bl[0][0] = Wl[wf]; bl[0][1] = Wl[wf + 32];
    }
#pragma unroll
    for (int s = 0; s < 16; s++) {
        const int cur = s & 3, wcur = s & 1, wnxt = wcur ^ 1;
        if (s + 3 < 16) {
            int af = ((kf0 + s + 3) * 2 + mf) * 32 + lane;
            ah[(s + 3) & 3] = Aph[af]; al[(s + 3) & 3] = Apl[af];
        }
        if (s < 15) {
            int wf = ((kf0 + s + 1) * 2) * 32 + lane;
            bh[wnxt][0] = Wh[wf]; bh[wnxt][1] = Wh[wf + 32];
            bl[wnxt][0] = Wl[wf]; bl[wnxt][1] = Wl[wf + 32];
        }
#pragma unroll
        for (int nf = 0; nf < 2; nf++) {
            mma16816(c[nf], &ah[cur].x, &bh[wcur][nf].x);
            mma16816(c[nf], &al[cur].x, &bh[wcur][nf].x);
            mma16816(c[nf], &ah[cur].x, &bl[wcur][nf].x);
        }
    }
    const int r = lane >> 2, c2 = (lane & 3) * 2;
#pragma unroll
    for (int nf = 0; nf < 2; nf++) {
        int off = kg * 640 + (mf * 16 + r) * 20 + nf * 8 + c2;
        *(float2*)(scr + off) = make_float2(c[nf][0], c[nf][1]);
        *(float2*)(scr + off + 8 * 20) = make_float2(c[nf][2], c[nf][3]);
    }
}

// reduce scr partials (4 kg) at (row, col-pair) -> float2
__device__ __forceinline__ float2 red4(const float* __restrict__ scr, int row, int col) {
    float a = 0.0f, b = 0.0f;
#pragma unroll
    for (int kg = 0; kg < 4; kg++) {
        float2 v = *(const float2*)(scr + kg * 640 + row * 20 + col);
        a += v.x; b += v.y;
    }
    return make_float2(a, b);
}

__global__ void __launch_bounds__(256, 1) gru_step_kernel(
    const float* __restrict__ h0in,
    const float* __restrict__ Whz, const float* __restrict__ Whr,
    const float* __restrict__ Whh,
    const float* __restrict__ Whz_b, const float* __restrict__ Whr_b,
    const float* __restrict__ Whh_b,
    const float* __restrict__ Wiz_b, const float* __restrict__ Wir_b,
    const float* __restrict__ Wih_b,
    const void* __restrict__ lengths,
    float* __restrict__ out, int write_last)
{
    extern __shared__ char sm[];
    uint2* Wzh = (uint2*)(sm + W_ZH);
    uint2* Wzl = (uint2*)(sm + W_ZL);
    uint2* Wrh = (uint2*)(sm + W_RH);
    uint2* Wrl = (uint2*)(sm + W_RL);
    uint2* Wch = (uint2*)(sm + W_CH);
    uint2* Wcl = (uint2*)(sm + W_CL);
    float* scrz = (float*)(sm + PB_SCRZ);
    float* scrr = (float*)(sm + PB_SCRR);
    float* bia = (float*)(sm + PB_BIA);     // [0:16) z, [16:32) r, [32:48) c
    int* slen = (int*)(sm + PB_SLEN);

    const int tid = threadIdx.x, wid = tid >> 5, lane = tid & 31;
    const int b = blockIdx.x;
    const int half = b >> 6;
    const int j = b & 63;
    const int gn0 = j * 16;
    const int row0 = half * 32;

    packW(Whz, gn0, Wzh, Wzl, tid);
    packW(Whr, gn0, Wrh, Wrl, tid);
    packW(Whh, gn0, Wch, Wcl, tid);
    if (tid < 16) {
        bia[tid]      = Whz_b[gn0 + tid] + Wiz_b[gn0 + tid];
        bia[16 + tid] = Whr_b[gn0 + tid] + Wir_b[gn0 + tid];
        bia[32 + tid] = Whh_b[gn0 + tid] + Wih_b[gn0 + tid];
    }
    {   // lengths dtype auto-detect (int64 -> high word of elem0 is 0)
        const int* L32 = (const int*)lengths;
        int is64 = (L32[1] == 0);
        if (tid < 32) {
            int rr = row0 + tid;
            slen[tid] = is64 ? (int)((const long long*)lengths)[rr] : L32[rr];
        }
    }

    // frag-thread geometry (tid < 64): owns A-frag (j*2+mf, lane)
    const int fmf = tid >> 5;            // mf (valid for tid<64)
    const int fl = lane;
    const int fr = fl >> 2, fc = (fl & 3) * 2;
    const int ra = fmf * 16 + fr, rb = ra + 8;
    const int fi = (j * 2 + fmf) * 32 + fl;
    // 8 owned positions: (ra,fc/fc+1), (rb,fc/fc+1), (ra,fc+8/9), (rb,fc+8/9)
    const size_t gra = (size_t)(row0 + ra) * NH + gn0;
    const size_t grb = (size_t)(row0 + rb) * NH + gn0;
    float hv[8];                // h values (frag threads only)
    float zv[8];                // z gate, carried epi1 -> epi2

    if (tid < 64) {             // init h + publish frags
        float2 a0 = *(const float2*)(h0in + gra + fc);
        float2 b0 = *(const float2*)(h0in + grb + fc);
        float2 a8 = *(const float2*)(h0in + gra + fc + 8);
        float2 b8 = *(const float2*)(h0in + grb + fc + 8);
        hv[0] = a0.x; hv[1] = a0.y; hv[2] = b0.x; hv[3] = b0.y;
        hv[4] = a8.x; hv[5] = a8.y; hv[6] = b8.x; hv[7] = b8.y;
        uint32_t ph[4], pl[4];
        splitp(hv[0], hv[1], ph[0], pl[0]);
        splitp(hv[2], hv[3], ph[1], pl[1]);
        splitp(hv[4], hv[5], ph[2], pl[2]);
        splitp(hv[6], hv[7], ph[3], pl[3]);
        g_hhf[0][half][fi] = make_uint4(ph[0], ph[1], ph[2], ph[3]);
        g_hlf[0][half][fi] = make_uint4(pl[0], pl[1], pl[2], pl[3]);
    }
    __syncthreads();
    if (tid == 0) { __threadfence(); st_rel(&g_fh[half * 64 + j], 0); }

    int sla = 0, slb = 0;
    if (tid < 64) { sla = slen[ra]; slb = slen[rb]; }
    const size_t GATE = (size_t)TSTEPS * BATCH * NH;
    const int* fhb = g_fh + half * 64;
    const int* frhb = g_frh + half * 64;
    const uint4* hhfp[2] = {g_hhf[0][half], g_hhf[1][half]};
    const uint4* hlfp[2] = {g_hlf[0][half], g_hlf[1][half]};
    uint4* rhh = g_rhhf[half];
    uint4* rhl = g_rhlf[half];

    for (int t = 0; t < TSTEPS; t++) {
        const size_t xoff = (size_t)t * BATCH * NH;
        // ---- fused z+r gemm ----
        block_wait64(fhb, t);
        gemm_zr(hhfp[t & 1], hlfp[t & 1], Wzh, Wzl, Wrh, Wrl, scrz, scrr, wid, lane);
        __syncthreads();
        // ---- epi1 (frag threads): z regs, rh -> direct frag publish ----
        if (tid < 64) {
            float rv[8];
            {
                float2 s;
                s = red4(scrz, ra, fc);     zv[0] = s.x; zv[1] = s.y;
                s = red4(scrz, rb, fc);     zv[2] = s.x; zv[3] = s.y;
                s = red4(scrz, ra, fc + 8); zv[4] = s.x; zv[5] = s.y;
                s = red4(scrz, rb, fc + 8); zv[6] = s.x; zv[7] = s.y;
                s = red4(scrr, ra, fc);     rv[0] = s.x; rv[1] = s.y;
                s = red4(scrr, rb, fc);     rv[2] = s.x; rv[3] = s.y;
                s = red4(scrr, ra, fc + 8); rv[4] = s.x; rv[5] = s.y;
                s = red4(scrr, rb, fc + 8); rv[6] = s.x; rv[7] = s.y;
            }
            {
                float2 xa0 = *(const float2*)(g_X + xoff + gra + fc);
                float2 xb0 = *(const float2*)(g_X + xoff + grb + fc);
                float2 xa8 = *(const float2*)(g_X + xoff + gra + fc + 8);
                float2 xb8 = *(const float2*)(g_X + xoff + grb + fc + 8);
                zv[0] += bia[fc] + xa0.x;     zv[1] += bia[fc + 1] + xa0.y;
                zv[2] += bia[fc] + xb0.x;     zv[3] += bia[fc + 1] + xb0.y;
                zv[4] += bia[fc + 8] + xa8.x; zv[5] += bia[fc + 9] + xa8.y;
                zv[6] += bia[fc + 8] + xb8.x; zv[7] += bia[fc + 9] + xb8.y;
            }
            {
                float2 xa0 = *(const float2*)(g_X + GATE + xoff + gra + fc);
                float2 xb0 = *(const float2*)(g_X + GATE + xoff + grb + fc);
                float2 xa8 = *(const float2*)(g_X + GATE + xoff + gra + fc + 8);
                float2 xb8 = *(const float2*)(g_X + GATE + xoff + grb + fc + 8);
                rv[0] += bia[16 + fc] + xa0.x;     rv[1] += bia[17 + fc] + xa0.y;
                rv[2] += bia[16 + fc] + xb0.x;     rv[3] += bia[17 + fc] + xb0.y;
                rv[4] += bia[24 + fc] + xa8.x;     rv[5] += bia[25 + fc] + xa8.y;
                rv[6] += bia[24 + fc] + xb8.x;     rv[7] += bia[25 + fc] + xb8.y;
            }
            uint32_t ph[4], pl[4];
#pragma unroll
            for (int q = 0; q < 8; q++) {
                zv[q] = 1.0f / (1.0f + expf(-zv[q]));
                rv[q] = 1.0f / (1.0f + expf(-rv[q])) * hv[q];
            }
            splitp(rv[0], rv[1], ph[0], pl[0]);
            splitp(rv[2], rv[3], ph[1], pl[1]);
            splitp(rv[4], rv[5], ph[2], pl[2]);
            splitp(rv[6], rv[7], ph[3], pl[3]);
            rhh[fi] = make_uint4(ph[0], ph[1], ph[2], ph[3]);
            rhl[fi] = make_uint4(pl[0], pl[1], pl[2], pl[3]);
        }
        __syncthreads();
        if (tid == 0) { __threadfence(); st_rel(&g_frh[half * 64 + j], t + 1); }
        // ---- candidate gemm ----
        block_wait64(frhb, t + 1);
        gemm_c(rhh, rhl, Wch, Wcl, scrz, wid, lane);
        __syncthreads();
        // ---- epi2 (frag threads): update h, publish frags + out ----
        if (tid < 64) {
            float pv[8];
            {
                float2 s;
                s = red4(scrz, ra, fc);     pv[0] = s.x; pv[1] = s.y;
                s = red4(scrz, rb, fc);     pv[2] = s.x; pv[3] = s.y;
                s = red4(scrz, ra, fc + 8); pv[4] = s.x; pv[5] = s.y;
                s = red4(scrz, rb, fc + 8); pv[6] = s.x; pv[7] = s.y;
            }
            {
                float2 xa0 = *(const float2*)(g_X + 2 * GATE + xoff + gra + fc);
                float2 xb0 = *(const float2*)(g_X + 2 * GATE + xoff + grb + fc);
                float2 xa8 = *(const float2*)(g_X + 2 * GATE + xoff + gra + fc + 8);
                float2 xb8 = *(const float2*)(g_X + 2 * GATE + xoff + grb + fc + 8);
                pv[0] += bia[32 + fc] + xa0.x;     pv[1] += bia[33 + fc] + xa0.y;
                pv[2] += bia[32 + fc] + xb0.x;     pv[3] += bia[33 + fc] + xb0.y;
                pv[4] += bia[40 + fc] + xa8.x;     pv[5] += bia[41 + fc] + xa8.y;
                pv[6] += bia[40 + fc] + xb8.x;     pv[7] += bia[41 + fc] + xb8.y;
            }
#pragma unroll
            for (int q = 0; q < 8; q++) {
                float hc = tanhf(pv[q]);
                float hn = (1.0f - zv[q]) * hv[q] + zv[q] * hc;
                int rsl = (q == 2 || q == 3 || q == 6 || q == 7) ? slb : sla;
                if (t >= rsl) hn = hv[q];
                hv[q] = hn;
            }
            uint32_t ph[4], pl[4];
            splitp(hv[0], hv[1], ph[0], pl[0]);
            splitp(hv[2], hv[3], ph[1], pl[1]);
            splitp(hv[4], hv[5], ph[2], pl[2]);
            splitp(hv[6], hv[7], ph[3], pl[3]);
            g_hhf[(t + 1) & 1][half][fi] = make_uint4(ph[0], ph[1], ph[2], ph[3]);
            g_hlf[(t + 1) & 1][half][fi] = make_uint4(pl[0], pl[1], pl[2], pl[3]);
            *(float2*)(out + xoff + gra + fc) = make_float2(hv[0], hv[1]);
            *(float2*)(out + xoff + grb + fc) = make_float2(hv[2], hv[3]);
            *(float2*)(out + xoff + gra + fc + 8) = make_float2(hv[4], hv[5]);
            *(float2*)(out + xoff + grb + fc + 8) = make_float2(hv[6], hv[7]);
        }
        __syncthreads();
        if (tid == 0) { __threadfence(); st_rel(&g_fh[half * 64 + j], t + 1); }
    }
    if (write_last && tid < 64) {
        const size_t lo = (size_t)TSTEPS * BATCH * NH;
        *(float2*)(out + lo + gra + fc) = make_float2(hv[0], hv[1]);
        *(float2*)(out + lo + grb + fc) = make_float2(hv[2], hv[3]);
        *(float2*)(out + lo + gra + fc + 8) = make_float2(hv[4], hv[5]);
        *(float2*)(out + lo + grb + fc + 8) = make_float2(hv[6], hv[7]);
    }
}

// ============================= launch =======================================
extern "C" void kernel_launch(void* const* d_in, const int* in_sizes, int n_in,
                              void* d_out, int out_size)
{
    const float* input = (const float*)d_in[0];
    const float* h0    = (const float*)d_in[1];
    const float* Wiz_w = (const float*)d_in[2];
    const float* Wiz_b = (const float*)d_in[3];
    const float* Wir_w = (const float*)d_in[4];
    const float* Wir_b = (const float*)d_in[5];
    const float* Wih_w = (const float*)d_in[6];
    const float* Wih_b = (const float*)d_in[7];
    const float* Whz_w = (const float*)d_in[8];
    const float* Whz_b = (const float*)d_in[9];
    const float* Whr_w = (const float*)d_in[10];
    const float* Whr_b = (const float*)d_in[11];
    const float* Whh_w = (const float*)d_in[12];
    const float* Whh_b = (const float*)d_in[13];
    const void*  lengths = d_in[14];

    cudaFuncSetAttribute(input_proj_kernel,
                         cudaFuncAttributeMaxDynamicSharedMemorySize, PA_SMEM);
    cudaFuncSetAttribute(gru_step_kernel,
                         cudaFuncAttributeMaxDynamicSharedMemorySize, PB_SMEM);

    init_misc_kernel<<<1, 128>>>();
    input_proj_kernel<<<256 * 24, 256, PA_SMEM>>>(input, Wiz_w, Wir_w, Wih_w);

    int write_last = (out_size >= TSTEPS * BATCH * NH + BATCH * NH) ? 1 : 0;
    gru_step_kernel<<<NBLK, 256, PB_SMEM>>>(
        h0, Whz_w, Whr_w, Whh_w, Whz_b, Whr_b, Whh_b,
        Wiz_b, Wir_b, Wih_b, lengths, (float*)d_out, write_last);
}

// round 14
// speedup vs baseline: 1.0034x; 1.0034x over previous
#include <cuda_runtime.h>
#include <cuda_bf16.h>
#include <cstdint>
#include <math.h>

#define TSTEPS 512
#define BATCH  64
#define NIN    512
#define NH     1024
#define NBLK   128

// ============================ global scratch ================================
__device__ float g_X[(size_t)3 * TSTEPS * BATCH * NH];   // input projections
// A-operand planes, frag order per half: (kf*2+mf)*32+lane, kf 0..63, mf 0..1
__device__ uint4 g_hhf[2][2][4096], g_hlf[2][2][4096];   // h planes [parity][half]
__device__ uint4 g_rhhf[2][4096], g_rhlf[2][4096];       // r*h planes [half]
__device__ int g_fh[128], g_frh[128];                    // flags [j + 64*half]

// ============================ helpers =======================================
__device__ __forceinline__ uint32_t bfpack(float x, float y) {
    __nv_bfloat162 t = __floats2bfloat162_rn(x, y);
    return *(uint32_t*)&t;
}
__device__ __forceinline__ void splitp(float x, float y, uint32_t& hi, uint32_t& lo) {
    float hx = __bfloat162float(__float2bfloat16(x));
    float hy = __bfloat162float(__float2bfloat16(y));
    hi = bfpack(hx, hy);
    lo = bfpack(x - hx, y - hy);
}
__device__ __forceinline__ void mma16816(float* c, const uint32_t* a, const uint32_t* b) {
    asm volatile("mma.sync.aligned.m16n8k16.row.col.f32.bf16.bf16.f32 "
        "{%0,%1,%2,%3},{%4,%5,%6,%7},{%8,%9},{%0,%1,%2,%3};"
        : "+f"(c[0]), "+f"(c[1]), "+f"(c[2]), "+f"(c[3])
        : "r"(a[0]), "r"(a[1]), "r"(a[2]), "r"(a[3]), "r"(b[0]), "r"(b[1]));
}
__device__ __forceinline__ int ld_acq(const int* p) {
    int v;
    asm volatile("ld.acquire.gpu.global.s32 %0, [%1];" : "=r"(v) : "l"(p) : "memory");
    return v;
}
__device__ __forceinline__ void st_rel(int* p, int v) {
    asm volatile("st.release.gpu.global.s32 [%0], %1;" :: "l"(p), "r"(v) : "memory");
}
// single-warp polling of 64 flags (warp 0), block released by syncthreads
__device__ __forceinline__ void block_wait64(const int* flags, int target) {
    if (threadIdx.x < 32) {
        const int* p0 = flags + threadIdx.x;
        const int* p1 = flags + 32 + threadIdx.x;
        while (!__all_sync(0xFFFFFFFFu,
                           (ld_acq(p0) >= target) && (ld_acq(p1) >= target)))
            __nanosleep(60);
    }
    __syncthreads();
}

// =================== init: reset flags each launch ==========================
__global__ void init_misc_kernel() {
    int i = threadIdx.x;
    if (i < 128) { g_fh[i] = -1; g_frh[i] = -1; }
}

// ======================= phase A: input projections =========================
#define PA_AH 0
#define PA_AL 32768
#define PA_WH 65536
#define PA_WL 98304
#define PA_SMEM 131072

__global__ void __launch_bounds__(256) input_proj_kernel(
    const float* __restrict__ input,
    const float* __restrict__ Wiz, const float* __restrict__ Wir,
    const float* __restrict__ Wih)
{
    extern __shared__ char sm[];
    uint4* Ah = (uint4*)(sm + PA_AH);
    uint4* Al = (uint4*)(sm + PA_AL);
    uint2* Wh = (uint2*)(sm + PA_WH);
    uint2* Wl = (uint2*)(sm + PA_WL);
    const int tid = threadIdx.x, wid = tid >> 5, lane = tid & 31;
    const int ntile = blockIdx.x % 24, mtile = blockIdx.x / 24;
    const int gate = ntile >> 3, n0g = (ntile & 7) * 128, m0 = mtile * 128;
    const float* W = (gate == 0) ? Wiz : ((gate == 1) ? Wir : Wih);
    const int mg = wid & 3, ng = wid >> 2;

    float c[2][8][4];
#pragma unroll
    for (int i = 0; i < 2; i++)
#pragma unroll
        for (int j = 0; j < 8; j++)
#pragma unroll
            for (int k = 0; k < 4; k++) c[i][j][k] = 0.0f;

    for (int ch = 0; ch < 4; ch++) {
        const int k0 = ch * 128;
        __syncthreads();
#pragma unroll
        for (int it = 0; it < 8; it++) {
            int idx = tid + (it << 8);
            int frag = idx >> 5, l = idx & 31;
            int kf = frag >> 3, mf = frag & 7;
            int r = l >> 2, c2 = (l & 3) * 2;
            const float* src = input + (size_t)(m0 + mf * 16 + r) * NIN + k0 + kf * 16 + c2;
            float2 p0 = *(const float2*)(src);
            float2 p1 = *(const float2*)(src + 8 * NIN);
            float2 p2 = *(const float2*)(src + 8);
            float2 p3 = *(const float2*)(src + 8 * NIN + 8);
            uint32_t h0, h1, h2, h3, lo0, lo1, lo2, lo3;
            splitp(p0.x, p0.y, h0, lo0); splitp(p1.x, p1.y, h1, lo1);
            splitp(p2.x, p2.y, h2, lo2); splitp(p3.x, p3.y, h3, lo3);
            Ah[frag * 32 + l] = make_uint4(h0, h1, h2, h3);
            Al[frag * 32 + l] = make_uint4(lo0, lo1, lo2, lo3);
        }
#pragma unroll
        for (int it = 0; it < 16; it++) {
            int idx = tid + (it << 8);
            int frag = idx >> 5, l = idx & 31;
            int kf = frag >> 4, nf = frag & 15;
            int n = nf * 8 + (l >> 2), k = kf * 16 + (l & 3) * 2;
            const float* src = W + (size_t)(n0g + n) * NIN + k0 + k;
            float2 q0 = *(const float2*)src;
            float2 q1 = *(const float2*)(src + 8);
            uint32_t h0, h1, lo0, lo1;
            splitp(q0.x, q0.y, h0, lo0); splitp(q1.x, q1.y, h1, lo1);
            Wh[frag * 32 + l] = make_uint2(h0, h1);
            Wl[frag * 32 + l] = make_uint2(lo0, lo1);
        }
        __syncthreads();
#pragma unroll 2
        for (int s = 0; s < 8; s++) {
            uint4 ah[2], al[2];
            uint2 bh[8], bl[8];
            ah[0] = Ah[(s * 8 + mg * 2 + 0) * 32 + lane];
            ah[1] = Ah[(s * 8 + mg * 2 + 1) * 32 + lane];
            al[0] = Al[(s * 8 + mg * 2 + 0) * 32 + lane];
            al[1] = Al[(s * 8 + mg * 2 + 1) * 32 + lane];
#pragma unroll
            for (int nf = 0; nf < 8; nf++) {
                bh[nf] = Wh[(s * 16 + ng * 8 + nf) * 32 + lane];
                bl[nf] = Wl[(s * 16 + ng * 8 + nf) * 32 + lane];
            }
#pragma unroll
            for (int mf = 0; mf < 2; mf++)
#pragma unroll
                for (int nf = 0; nf < 8; nf++) {
                    mma16816(c[mf][nf], &ah[mf].x, &bh[nf].x);
                    mma16816(c[mf][nf], &al[mf].x, &bh[nf].x);
                    mma16816(c[mf][nf], &ah[mf].x, &bl[nf].x);
                }
        }
    }
    const int r = lane >> 2, c2 = (lane & 3) * 2;
#pragma unroll
    for (int mf = 0; mf < 2; mf++)
#pragma unroll
        for (int nf = 0; nf < 8; nf++) {
            size_t row = (size_t)(m0 + (mg * 2 + mf) * 16 + r);
            size_t base = ((size_t)gate * TSTEPS * BATCH + row) * NH
                        + n0g + (ng * 8 + nf) * 8 + c2;
            *(float2*)(g_X + base) = make_float2(c[mf][nf][0], c[mf][nf][1]);
            *(float2*)(g_X + base + (size_t)8 * NH) = make_float2(c[mf][nf][2], c[mf][nf][3]);
        }
}

// ======================= phase B: persistent GRU ============================
// 128 blocks = 2 independent chains (half = batch rows 0-31 / 32-63).
// Block (half, j): 32 rows x 16 cols of z, r, rh, candidate, h. 2 hops/step.
#define W_ZH 0          // 128 frags x 32 x 8B = 32768 per plane
#define W_ZL 32768
#define W_RH 65536
#define W_RL 98304
#define W_CH 131072
#define W_CL 163840
#define PB_SCRZ 196608  // float[4][32][20] = 10240
#define PB_SCRR 206848  // float[4][32][20] = 10240
#define PB_SBUF 217088  // float[32][20]    =  2560
#define PB_BIA  219648  // float[48]: z|r|c
#define PB_SLEN 219840  // int[32]
#define PB_SMEM 220160

// pack full-K W slice (16 cols x 1024) into 128 B-frag-order split frags
__device__ __forceinline__ void packW(const float* __restrict__ W, int gn0,
                                      uint2* __restrict__ Dh, uint2* __restrict__ Dl,
                                      int tid)
{
#pragma unroll 4
    for (int it = 0; it < 16; it++) {
        int idx = tid + (it << 8);
        int frag = idx >> 5, l = idx & 31;
        int kf = frag >> 1, nf = frag & 1;
        int n = nf * 8 + (l >> 2), k = kf * 16 + (l & 3) * 2;
        const float* src = W + (size_t)(gn0 + n) * NH + k;
        float2 q0 = *(const float2*)src;
        float2 q1 = *(const float2*)(src + 8);
        uint32_t h0, h1, lo0, lo1;
        splitp(q0.x, q0.y, h0, lo0); splitp(q1.x, q1.y, h1, lo1);
        Dh[frag * 32 + l] = make_uint2(h0, h1);
        Dl[frag * 32 + l] = make_uint2(lo0, lo1);
    }
}

// fused z+r gemm: C[32x16] x2 = A[32x1024] @ {Wz,Wr}^T. A read once.
// 8 warps: mf = wid&1 (16 rows), kg = wid>>1 (4 groups x 16 kf). 3-term.
// Depth-4 A prefetch (A from L2), depth-2 W (SMEM).
__device__ __forceinline__ void gemm_zr(const uint4* __restrict__ Aph,
                                        const uint4* __restrict__ Apl,
                                        const uint2* __restrict__ Wzh, const uint2* __restrict__ Wzl,
                                        const uint2* __restrict__ Wrh, const uint2* __restrict__ Wrl,
                                        float* __restrict__ scrz, float* __restrict__ scrr,
                                        int wid, int lane)
{
    const int mf = wid & 1, kg = wid >> 1;
    const int kf0 = kg * 16;
    float cz[2][4], cr[2][4];
#pragma unroll
    for (int j = 0; j < 2; j++)
#pragma unroll
        for (int k = 0; k < 4; k++) { cz[j][k] = 0.0f; cr[j][k] = 0.0f; }

    uint4 ah[4], al[4];
    uint2 bzh[2][2], bzl[2][2], brh[2][2], brl[2][2];
#pragma unroll
    for (int p = 0; p < 3; p++) {
        int af = ((kf0 + p) * 2 + mf) * 32 + lane;
        ah[p] = Aph[af]; al[p] = Apl[af];
    }
    {
        int wf = (kf0 * 2) * 32 + lane;
        bzh[0][0] = Wzh[wf]; bzh[0][1] = Wzh[wf + 32];
        bzl[0][0] = Wzl[wf]; bzl[0][1] = Wzl[wf + 32];
        brh[0][0] = Wrh[wf]; brh[0][1] = Wrh[wf + 32];
        brl[0][0] = Wrl[wf]; brl[0][1] = Wrl[wf + 32];
    }
#pragma unroll
    for (int s = 0; s < 16; s++) {
        const int cur = s & 3, wcur = s & 1, wnxt = wcur ^ 1;
        if (s + 3 < 16) {
            int af = ((kf0 + s + 3) * 2 + mf) * 32 + lane;
            ah[(s + 3) & 3] = Aph[af]; al[(s + 3) & 3] = Apl[af];
        }
        if (s < 15) {
            int wf = ((kf0 + s + 1) * 2) * 32 + lane;
            bzh[wnxt][0] = Wzh[wf]; bzh[wnxt][1] = Wzh[wf + 32];
            bzl[wnxt][0] = Wzl[wf]; bzl[wnxt][1] = Wzl[wf + 32];
            brh[wnxt][0] = Wrh[wf]; brh[wnxt][1] = Wrh[wf + 32];
            brl[wnxt][0] = Wrl[wf]; brl[wnxt][1] = Wrl[wf + 32];
        }
#pragma unroll
        for (int nf = 0; nf < 2; nf++) {
            mma16816(cz[nf], &ah[cur].x, &bzh[wcur][nf].x);
            mma16816(cz[nf], &al[cur].x, &bzh[wcur][nf].x);
            mma16816(cz[nf], &ah[cur].x, &bzl[wcur][nf].x);
            mma16816(cr[nf], &ah[cur].x, &brh[wcur][nf].x);
            mma16816(cr[nf], &al[cur].x, &brh[wcur][nf].x);
            mma16816(cr[nf], &ah[cur].x, &brl[wcur][nf].x);
        }
    }
    const int r = lane >> 2, c2 = (lane & 3) * 2;
#pragma unroll
    for (int nf = 0; nf < 2; nf++) {
        int off = kg * 640 + (mf * 16 + r) * 20 + nf * 8 + c2;
        *(float2*)(scrz + off) = make_float2(cz[nf][0], cz[nf][1]);
        *(float2*)(scrz + off + 8 * 20) = make_float2(cz[nf][2], cz[nf][3]);
        *(float2*)(scrr + off) = make_float2(cr[nf][0], cr[nf][1]);
        *(float2*)(scrr + off + 8 * 20) = make_float2(cr[nf][2], cr[nf][3]);
    }
}

// candidate gemm: C[32x16] = RH[32x1024] @ Wc^T. Depth-4 A prefetch.
__device__ __forceinline__ void gemm_c(const uint4* __restrict__ Aph,
                                       const uint4* __restrict__ Apl,
                                       const uint2* __restrict__ Wh,
                                       const uint2* __restrict__ Wl,
                                       float* __restrict__ scr,
                                       int wid, int lane)
{
    const int mf = wid & 1, kg = wid >> 1;
    const int kf0 = kg * 16;
    float c[2][4];
#pragma unroll
    for (int j = 0; j < 2; j++)
#pragma unroll
        for (int k = 0; k < 4; k++) c[j][k] = 0.0f;

    uint4 ah[4], al[4];
    uint2 bh[2][2], bl[2][2];
#pragma unroll
    for (int p = 0; p < 3; p++) {
        int af = ((kf0 + p) * 2 + mf) * 32 + lane;
        ah[p] = Aph[af]; al[p] = Apl[af];
    }
    {
        int wf = (kf0 * 2) * 32 + lane;
        bh[0][0] = Wh[wf]; bh[0][1] = Wh[wf + 32];
        bl[0][0] = Wl[wf]; bl[0][1] = Wl[wf + 32];
    }
#pragma unroll
    for (int s = 0; s < 16; s++) {
        const int cur = s & 3, wcur = s & 1, wnxt = wcur ^ 1;
        if (s + 3 < 16) {
            int af = ((kf0 + s + 3) * 2 + mf) * 32 + lane;
            ah[(s + 3) & 3] = Aph[af]; al[(s + 3) & 3] = Apl[af];
        }
        if (s < 15) {
            int wf = ((kf0 + s + 1) * 2) * 32 + lane;
            bh[wnxt][0] = Wh[wf]; bh[wnxt][1] = Wh[wf + 32];
            bl[wnxt][0] = Wl[wf]; bl[wnxt][1] = Wl[wf + 32];
        }
#pragma unroll
        for (int nf = 0; nf < 2; nf++) {
            mma16816(c[nf], &ah[cur].x, &bh[wcur][nf].x);
            mma16816(c[nf], &al[cur].x, &bh[wcur][nf].x);
            mma16816(c[nf], &ah[cur].x, &bl[wcur][nf].x);
        }
    }
    const int r = lane >> 2, c2 = (lane & 3) * 2;
#pragma unroll
    for (int nf = 0; nf < 2; nf++) {
        int off = kg * 640 + (mf * 16 + r) * 20 + nf * 8 + c2;
        *(float2*)(scr + off) = make_float2(c[nf][0], c[nf][1]);
        *(float2*)(scr + off + 8 * 20) = make_float2(c[nf][2], c[nf][3]);
    }
}

// pack sbuf[32][20] (16 cols) into 2 A-frags at kf = j (warps 0-1)
__device__ __forceinline__ void pack2(const float* __restrict__ sbuf,
                                      uint4* __restrict__ dsth,
                                      uint4* __restrict__ dstl,
                                      int jkf, int wid, int lane)
{
    if (wid < 2) {
        const int mf = wid;
        const int r = lane >> 2, c2 = (lane & 3) * 2;
        const float* p = sbuf + (mf * 16 + r) * 20 + c2;
        uint32_t h0, h1, h2, h3, l0, l1, l2, l3;
        splitp(p[0], p[1], h0, l0);
        splitp(p[160], p[161], h1, l1);
        splitp(p[8], p[9], h2, l2);
        splitp(p[168], p[169], h3, l3);
        const int fi = (jkf * 2 + mf) * 32 + lane;
        dsth[fi] = make_uint4(h0, h1, h2, h3);
        dstl[fi] = make_uint4(l0, l1, l2, l3);
    }
}

__global__ void __launch_bounds__(256, 1) gru_step_kernel(
    const float* __restrict__ h0in,
    const float* __restrict__ Whz, const float* __restrict__ Whr,
    const float* __restrict__ Whh,
    const float* __restrict__ Whz_b, const float* __restrict__ Whr_b,
    const float* __restrict__ Whh_b,
    const float* __restrict__ Wiz_b, const float* __restrict__ Wir_b,
    const float* __restrict__ Wih_b,
    const void* __restrict__ lengths,
    float* __restrict__ out, int write_last)
{
    extern __shared__ char sm[];
    uint2* Wzh = (uint2*)(sm + W_ZH);
    uint2* Wzl = (uint2*)(sm + W_ZL);
    uint2* Wrh = (uint2*)(sm + W_RH);
    uint2* Wrl = (uint2*)(sm + W_RL);
    uint2* Wch = (uint2*)(sm + W_CH);
    uint2* Wcl = (uint2*)(sm + W_CL);
    float* scrz = (float*)(sm + PB_SCRZ);
    float* scrr = (float*)(sm + PB_SCRR);
    float* sbuf = (float*)(sm + PB_SBUF);
    float* bia = (float*)(sm + PB_BIA);     // [0:16) z, [16:32) r, [32:48) c
    int* slen = (int*)(sm + PB_SLEN);

    const int tid = threadIdx.x, wid = tid >> 5, lane = tid & 31;
    const int b = blockIdx.x;
    const int half = b >> 6;
    const int j = b & 63;
    const int gn0 = j * 16;
    const int row0 = half * 32;

    packW(Whz, gn0, Wzh, Wzl, tid);
    packW(Whr, gn0, Wrh, Wrl, tid);
    packW(Whh, gn0, Wch, Wcl, tid);
    if (tid < 16) {
        bia[tid]      = Whz_b[gn0 + tid] + Wiz_b[gn0 + tid];
        bia[16 + tid] = Whr_b[gn0 + tid] + Wir_b[gn0 + tid];
        bia[32 + tid] = Whh_b[gn0 + tid] + Wih_b[gn0 + tid];
    }
    {   // lengths dtype auto-detect (int64 -> high word of elem0 is 0)
        const int* L32 = (const int*)lengths;
        int is64 = (L32[1] == 0);
        if (tid < 32) {
            int rr = row0 + tid;
            slen[tid] = is64 ? (int)((const long long*)lengths)[rr] : L32[rr];
        }
    }

    const int m = tid >> 3;          // 0..31
    const int nq = (tid & 7) * 2;    // 0..14
    const size_t xrow = (size_t)(row0 + m) * NH + gn0 + nq;
    float h0r, h1r;                  // local h tile (2 elems/thread)

    {   // init h
        float2 v = *(const float2*)(h0in + xrow);
        h0r = v.x; h1r = v.y;
        *(float2*)(sbuf + m * 20 + nq) = v;
        __syncthreads();
        pack2(sbuf, g_hhf[0][half], g_hlf[0][half], j, wid, lane);
        __syncthreads();
        if (tid == 0) { __threadfence(); st_rel(&g_fh[half * 64 + j], 0); }
    }

    const int sl = slen[m];
    const size_t GATE = (size_t)TSTEPS * BATCH * NH;
    const float* Xz = g_X + xrow;
    const float* Xr = g_X + GATE + xrow;
    const float* Xh = g_X + 2 * GATE + xrow;
    const int* fhb = g_fh + half * 64;
    const int* frhb = g_frh + half * 64;
    const uint4* hhfp[2] = {g_hhf[0][half], g_hhf[1][half]};
    const uint4* hlfp[2] = {g_hlf[0][half], g_hlf[1][half]};
    uint4* rhh = g_rhhf[half];
    uint4* rhl = g_rhlf[half];

    for (int t = 0; t < TSTEPS; t++) {
        float2 xz = *(const float2*)(Xz + (size_t)t * BATCH * NH);
        float2 xr = *(const float2*)(Xr + (size_t)t * BATCH * NH);
        float2 xh = *(const float2*)(Xh + (size_t)t * BATCH * NH);
        // ---- fused z+r gemm ----
        block_wait64(fhb, t);
        gemm_zr(hhfp[t & 1], hlfp[t & 1], Wzh, Wzl, Wrh, Wrl, scrz, scrr, wid, lane);
        __syncthreads();
        // ---- epi1: z (registers), rh -> sbuf ----
        float z0 = bia[nq] + xz.x, z1 = bia[nq + 1] + xz.y;
        float r0 = bia[16 + nq] + xr.x, r1 = bia[16 + nq + 1] + xr.y;
#pragma unroll
        for (int kg = 0; kg < 4; kg++) {
            float2 az = *(const float2*)(scrz + kg * 640 + m * 20 + nq);
            float2 ar = *(const float2*)(scrr + kg * 640 + m * 20 + nq);
            z0 += az.x; z1 += az.y;
            r0 += ar.x; r1 += ar.y;
        }
        z0 = 1.0f / (1.0f + expf(-z0));
        z1 = 1.0f / (1.0f + expf(-z1));
        r0 = 1.0f / (1.0f + expf(-r0));
        r1 = 1.0f / (1.0f + expf(-r1));
        *(float2*)(sbuf + m * 20 + nq) = make_float2(r0 * h0r, r1 * h1r);
        __syncthreads();
        pack2(sbuf, rhh, rhl, j, wid, lane);
        __syncthreads();
        if (tid == 0) { __threadfence(); st_rel(&g_frh[half * 64 + j], t + 1); }
        // ---- candidate gemm ----
        block_wait64(frhb, t + 1);
        gemm_c(rhh, rhl, Wch, Wcl, scrz, wid, lane);
        __syncthreads();
        // ---- epi2: update h ----
        float p0 = bia[32 + nq] + xh.x, p1 = bia[32 + nq + 1] + xh.y;
#pragma unroll
        for (int kg = 0; kg < 4; kg++) {
            float2 a = *(const float2*)(scrz + kg * 640 + m * 20 + nq);
            p0 += a.x; p1 += a.y;
        }
        float hn0 = (1.0f - z0) * h0r + z0 * tanhf(p0);
        float hn1 = (1.0f - z1) * h1r + z1 * tanhf(p1);
        if (t >= sl) { hn0 = h0r; hn1 = h1r; }
        h0r = hn0; h1r = hn1;
        *(float2*)(out + (size_t)t * BATCH * NH + xrow) = make_float2(hn0, hn1);
        *(float2*)(sbuf + m * 20 + nq) = make_float2(hn0, hn1);
        __syncthreads();
        pack2(sbuf, g_hhf[(t + 1) & 1][half], g_hlf[(t + 1) & 1][half], j, wid, lane);
        __syncthreads();
        if (tid == 0) { __threadfence(); st_rel(&g_fh[half * 64 + j], t + 1); }
    }
    if (write_last) {
        *(float2*)(out + (size_t)TSTEPS * BATCH * NH + xrow) = make_float2(h0r, h1r);
    }
}

// ============================= launch =======================================
extern "C" void kernel_launch(void* const* d_in, const int* in_sizes, int n_in,
                              void* d_out, int out_size)
{
    const float* input = (const float*)d_in[0];
    const float* h0    = (const float*)d_in[1];
    const float* Wiz_w = (const float*)d_in[2];
    const float* Wiz_b = (const float*)d_in[3];
    const float* Wir_w = (const float*)d_in[4];
    const float* Wir_b = (const float*)d_in[5];
    const float* Wih_w = (const float*)d_in[6];
    const float* Wih_b = (const float*)d_in[7];
    const float* Whz_w = (const float*)d_in[8];
    const float* Whz_b = (const float*)d_in[9];
    const float* Whr_w = (const float*)d_in[10];
    const float* Whr_b = (const float*)d_in[11];
    const float* Whh_w = (const float*)d_in[12];
    const float* Whh_b = (const float*)d_in[13];
    const void*  lengths = d_in[14];

    cudaFuncSetAttribute(input_proj_kernel,
                         cudaFuncAttributeMaxDynamicSharedMemorySize, PA_SMEM);
    cudaFuncSetAttribute(gru_step_kernel,
                         cudaFuncAttributeMaxDynamicSharedMemorySize, PB_SMEM);

    init_misc_kernel<<<1, 128>>>();
    input_proj_kernel<<<256 * 24, 256, PA_SMEM>>>(input, Wiz_w, Wir_w, Wih_w);

    int write_last = (out_size >= TSTEPS * BATCH * NH + BATCH * NH) ? 1 : 0;
    gru_step_kernel<<<NBLK, 256, PB_SMEM>>>(
        h0, Whz_w, Whr_w, Whh_w, Whz_b, Whr_b, Whh_b,
        Wiz_b, Wir_b, Wih_b, lengths, (float*)d_out, write_last);
}

// round 15
// speedup vs baseline: 1.1830x; 1.1790x over previous
#include <cuda_runtime.h>
#include <cuda_bf16.h>
#include <cstdint>
#include <math.h>

#define TSTEPS 512
#define BATCH  64
#define NIN    512
#define NH     1024
#define NBLK   128

// ============================ global scratch ================================
__device__ float g_X[(size_t)3 * TSTEPS * BATCH * NH];   // input projections
// A-operand planes, frag order per half: (kf*2+mf)*32+lane, kf 0..63, mf 0..1
__device__ uint4 g_hhf[2][2][4096], g_hlf[2][2][4096];   // h planes [parity][half]
__device__ uint4 g_rhhf[2][4096];                        // r*h hi plane [half]
__device__ int g_fh[128], g_frh[128];                    // flags [j + 64*half]

// ============================ helpers =======================================
__device__ __forceinline__ uint32_t bfpack(float x, float y) {
    __nv_bfloat162 t = __floats2bfloat162_rn(x, y);
    return *(uint32_t*)&t;
}
__device__ __forceinline__ void splitp(float x, float y, uint32_t& hi, uint32_t& lo) {
    float hx = __bfloat162float(__float2bfloat16(x));
    float hy = __bfloat162float(__float2bfloat16(y));
    hi = bfpack(hx, hy);
    lo = bfpack(x - hx, y - hy);
}
__device__ __forceinline__ void mma16816(float* c, const uint32_t* a, const uint32_t* b) {
    asm volatile("mma.sync.aligned.m16n8k16.row.col.f32.bf16.bf16.f32 "
        "{%0,%1,%2,%3},{%4,%5,%6,%7},{%8,%9},{%0,%1,%2,%3};"
        : "+f"(c[0]), "+f"(c[1]), "+f"(c[2]), "+f"(c[3])
        : "r"(a[0]), "r"(a[1]), "r"(a[2]), "r"(a[3]), "r"(b[0]), "r"(b[1]));
}
__device__ __forceinline__ int ld_acq(const int* p) {
    int v;
    asm volatile("ld.acquire.gpu.global.s32 %0, [%1];" : "=r"(v) : "l"(p) : "memory");
    return v;
}
__device__ __forceinline__ void st_rel(int* p, int v) {
    asm volatile("st.release.gpu.global.s32 [%0], %1;" :: "l"(p), "r"(v) : "memory");
}
// single-warp polling of 64 flags (warp 0), block released by syncthreads
__device__ __forceinline__ void block_wait64(const int* flags, int target) {
    if (threadIdx.x < 32) {
        const int* p0 = flags + threadIdx.x;
        const int* p1 = flags + 32 + threadIdx.x;
        while (!__all_sync(0xFFFFFFFFu,
                           (ld_acq(p0) >= target) && (ld_acq(p1) >= target)))
            __nanosleep(60);
    }
    __syncthreads();
}

// =================== init: reset flags each launch ==========================
__global__ void init_misc_kernel() {
    int i = threadIdx.x;
    if (i < 128) { g_fh[i] = -1; g_frh[i] = -1; }
}

// ======================= phase A: input projections =========================
#define PA_AH 0
#define PA_AL 32768
#define PA_WH 65536
#define PA_WL 98304
#define PA_SMEM 131072

__global__ void __launch_bounds__(256) input_proj_kernel(
    const float* __restrict__ input,
    const float* __restrict__ Wiz, const float* __restrict__ Wir,
    const float* __restrict__ Wih)
{
    extern __shared__ char sm[];
    uint4* Ah = (uint4*)(sm + PA_AH);
    uint4* Al = (uint4*)(sm + PA_AL);
    uint2* Wh = (uint2*)(sm + PA_WH);
    uint2* Wl = (uint2*)(sm + PA_WL);
    const int tid = threadIdx.x, wid = tid >> 5, lane = tid & 31;
    const int ntile = blockIdx.x % 24, mtile = blockIdx.x / 24;
    const int gate = ntile >> 3, n0g = (ntile & 7) * 128, m0 = mtile * 128;
    const float* W = (gate == 0) ? Wiz : ((gate == 1) ? Wir : Wih);
    const int mg = wid & 3, ng = wid >> 2;

    float c[2][8][4];
#pragma unroll
    for (int i = 0; i < 2; i++)
#pragma unroll
        for (int j = 0; j < 8; j++)
#pragma unroll
            for (int k = 0; k < 4; k++) c[i][j][k] = 0.0f;

    for (int ch = 0; ch < 4; ch++) {
        const int k0 = ch * 128;
        __syncthreads();
#pragma unroll
        for (int it = 0; it < 8; it++) {
            int idx = tid + (it << 8);
            int frag = idx >> 5, l = idx & 31;
            int kf = frag >> 3, mf = frag & 7;
            int r = l >> 2, c2 = (l & 3) * 2;
            const float* src = input + (size_t)(m0 + mf * 16 + r) * NIN + k0 + kf * 16 + c2;
            float2 p0 = *(const float2*)(src);
            float2 p1 = *(const float2*)(src + 8 * NIN);
            float2 p2 = *(const float2*)(src + 8);
            float2 p3 = *(const float2*)(src + 8 * NIN + 8);
            uint32_t h0, h1, h2, h3, lo0, lo1, lo2, lo3;
            splitp(p0.x, p0.y, h0, lo0); splitp(p1.x, p1.y, h1, lo1);
            splitp(p2.x, p2.y, h2, lo2); splitp(p3.x, p3.y, h3, lo3);
            Ah[frag * 32 + l] = make_uint4(h0, h1, h2, h3);
            Al[frag * 32 + l] = make_uint4(lo0, lo1, lo2, lo3);
        }
#pragma unroll
        for (int it = 0; it < 16; it++) {
            int idx = tid + (it << 8);
            int frag = idx >> 5, l = idx & 31;
            int kf = frag >> 4, nf = frag & 15;
            int n = nf * 8 + (l >> 2), k = kf * 16 + (l & 3) * 2;
            const float* src = W + (size_t)(n0g + n) * NIN + k0 + k;
            float2 q0 = *(const float2*)src;
            float2 q1 = *(const float2*)(src + 8);
            uint32_t h0, h1, lo0, lo1;
            splitp(q0.x, q0.y, h0, lo0); splitp(q1.x, q1.y, h1, lo1);
            Wh[frag * 32 + l] = make_uint2(h0, h1);
            Wl[frag * 32 + l] = make_uint2(lo0, lo1);
        }
        __syncthreads();
#pragma unroll 2
        for (int s = 0; s < 8; s++) {
            uint4 ah[2], al[2];
            uint2 bh[8], bl[8];
            ah[0] = Ah[(s * 8 + mg * 2 + 0) * 32 + lane];
            ah[1] = Ah[(s * 8 + mg * 2 + 1) * 32 + lane];
            al[0] = Al[(s * 8 + mg * 2 + 0) * 32 + lane];
            al[1] = Al[(s * 8 + mg * 2 + 1) * 32 + lane];
#pragma unroll
            for (int nf = 0; nf < 8; nf++) {
                bh[nf] = Wh[(s * 16 + ng * 8 + nf) * 32 + lane];
                bl[nf] = Wl[(s * 16 + ng * 8 + nf) * 32 + lane];
            }
#pragma unroll
            for (int mf = 0; mf < 2; mf++)
#pragma unroll
                for (int nf = 0; nf < 8; nf++) {
                    mma16816(c[mf][nf], &ah[mf].x, &bh[nf].x);
                    mma16816(c[mf][nf], &al[mf].x, &bh[nf].x);
                    mma16816(c[mf][nf], &ah[mf].x, &bl[nf].x);
                }
        }
    }
    const int r = lane >> 2, c2 = (lane & 3) * 2;
#pragma unroll
    for (int mf = 0; mf < 2; mf++)
#pragma unroll
        for (int nf = 0; nf < 8; nf++) {
            size_t row = (size_t)(m0 + (mg * 2 + mf) * 16 + r);
            size_t base = ((size_t)gate * TSTEPS * BATCH + row) * NH
                        + n0g + (ng * 8 + nf) * 8 + c2;
            *(float2*)(g_X + base) = make_float2(c[mf][nf][0], c[mf][nf][1]);
            *(float2*)(g_X + base + (size_t)8 * NH) = make_float2(c[mf][nf][2], c[mf][nf][3]);
        }
}

// ======================= phase B: persistent GRU ============================
// 128 blocks = 2 independent chains (half = batch rows 0-31 / 32-63).
// Block (half, j): 32 rows x 16 cols of z, r, rh, candidate, h. 2 hops/step.
// Candidate gemm is 2-term (rh hi-plane only): halves c-window L2 traffic.
#define W_ZH 0          // 128 frags x 32 x 8B = 32768 per plane
#define W_ZL 32768
#define W_RH 65536
#define W_RL 98304
#define W_CH 131072
#define W_CL 163840
#define PB_SCRZ 196608  // float[4][32][20] = 10240
#define PB_SCRR 206848  // float[4][32][20] = 10240
#define PB_SBUF 217088  // float[32][20]    =  2560
#define PB_BIA  219648  // float[48]: z|r|c
#define PB_SLEN 219840  // int[32]
#define PB_SMEM 220160

// pack full-K W slice (16 cols x 1024) into 128 B-frag-order split frags
__device__ __forceinline__ void packW(const float* __restrict__ W, int gn0,
                                      uint2* __restrict__ Dh, uint2* __restrict__ Dl,
                                      int tid)
{
#pragma unroll 4
    for (int it = 0; it < 16; it++) {
        int idx = tid + (it << 8);
        int frag = idx >> 5, l = idx & 31;
        int kf = frag >> 1, nf = frag & 1;
        int n = nf * 8 + (l >> 2), k = kf * 16 + (l & 3) * 2;
        const float* src = W + (size_t)(gn0 + n) * NH + k;
        float2 q0 = *(const float2*)src;
        float2 q1 = *(const float2*)(src + 8);
        uint32_t h0, h1, lo0, lo1;
        splitp(q0.x, q0.y, h0, lo0); splitp(q1.x, q1.y, h1, lo1);
        Dh[frag * 32 + l] = make_uint2(h0, h1);
        Dl[frag * 32 + l] = make_uint2(lo0, lo1);
    }
}

// fused z+r gemm: C[32x16] x2 = A[32x1024] @ {Wz,Wr}^T. A read once.
// 8 warps: mf = wid&1 (16 rows), kg = wid>>1 (4 groups x 16 kf). 3-term.
// Depth-2 operand pipeline (proven; depth-4 spills registers).
__device__ __forceinline__ void gemm_zr(const uint4* __restrict__ Aph,
                                        const uint4* __restrict__ Apl,
                                        const uint2* __restrict__ Wzh, const uint2* __restrict__ Wzl,
                                        const uint2* __restrict__ Wrh, const uint2* __restrict__ Wrl,
                                        float* __restrict__ scrz, float* __restrict__ scrr,
                                        int wid, int lane)
{
    const int mf = wid & 1, kg = wid >> 1;
    const int kf0 = kg * 16;
    float cz[2][4], cr[2][4];
#pragma unroll
    for (int j = 0; j < 2; j++)
#pragma unroll
        for (int k = 0; k < 4; k++) { cz[j][k] = 0.0f; cr[j][k] = 0.0f; }

    uint4 ah[2], al[2];
    uint2 bzh[2][2], bzl[2][2], brh[2][2], brl[2][2];
    {
        int af = (kf0 * 2 + mf) * 32 + lane;
        ah[0] = Aph[af]; al[0] = Apl[af];
        int wf = (kf0 * 2) * 32 + lane;
        bzh[0][0] = Wzh[wf]; bzh[0][1] = Wzh[wf + 32];
        bzl[0][0] = Wzl[wf]; bzl[0][1] = Wzl[wf + 32];
        brh[0][0] = Wrh[wf]; brh[0][1] = Wrh[wf + 32];
        brl[0][0] = Wrl[wf]; brl[0][1] = Wrl[wf + 32];
    }
#pragma unroll
    for (int s = 0; s < 16; s++) {
        const int cur = s & 1, nxt = cur ^ 1;
        if (s < 15) {
            int kf = kf0 + s + 1;
            int af = (kf * 2 + mf) * 32 + lane;
            ah[nxt] = Aph[af]; al[nxt] = Apl[af];
            int wf = (kf * 2) * 32 + lane;
            bzh[nxt][0] = Wzh[wf]; bzh[nxt][1] = Wzh[wf + 32];
            bzl[nxt][0] = Wzl[wf]; bzl[nxt][1] = Wzl[wf + 32];
            brh[nxt][0] = Wrh[wf]; brh[nxt][1] = Wrh[wf + 32];
            brl[nxt][0] = Wrl[wf]; brl[nxt][1] = Wrl[wf + 32];
        }
#pragma unroll
        for (int nf = 0; nf < 2; nf++) {
            mma16816(cz[nf], &ah[cur].x, &bzh[cur][nf].x);
            mma16816(cz[nf], &al[cur].x, &bzh[cur][nf].x);
            mma16816(cz[nf], &ah[cur].x, &bzl[cur][nf].x);
            mma16816(cr[nf], &ah[cur].x, &brh[cur][nf].x);
            mma16816(cr[nf], &al[cur].x, &brh[cur][nf].x);
            mma16816(cr[nf], &ah[cur].x, &brl[cur][nf].x);
        }
    }
    const int r = lane >> 2, c2 = (lane & 3) * 2;
#pragma unroll
    for (int nf = 0; nf < 2; nf++) {
        int off = kg * 640 + (mf * 16 + r) * 20 + nf * 8 + c2;
        *(float2*)(scrz + off) = make_float2(cz[nf][0], cz[nf][1]);
        *(float2*)(scrz + off + 8 * 20) = make_float2(cz[nf][2], cz[nf][3]);
        *(float2*)(scrr + off) = make_float2(cr[nf][0], cr[nf][1]);
        *(float2*)(scrr + off + 8 * 20) = make_float2(cr[nf][2], cr[nf][3]);
    }
}

// candidate gemm: C[32x16] = RH[32x1024] @ Wc^T, 2-term (rh hi-plane only):
// C = hi(rh)*hi(W) + hi(rh)*lo(W). Depth-2 pipeline.
__device__ __forceinline__ void gemm_c(const uint4* __restrict__ Aph,
                                       const uint2* __restrict__ Wh,
                                       const uint2* __restrict__ Wl,
                                       float* __restrict__ scr,
                                       int wid, int lane)
{
    const int mf = wid & 1, kg = wid >> 1;
    const int kf0 = kg * 16;
    float c[2][4];
#pragma unroll
    for (int j = 0; j < 2; j++)
#pragma unroll
        for (int k = 0; k < 4; k++) c[j][k] = 0.0f;

    uint4 ah[2];
    uint2 bh[2][2], bl[2][2];
    {
        int af = (kf0 * 2 + mf) * 32 + lane;
        ah[0] = Aph[af];
        int wf = (kf0 * 2) * 32 + lane;
        bh[0][0] = Wh[wf]; bh[0][1] = Wh[wf + 32];
        bl[0][0] = Wl[wf]; bl[0][1] = Wl[wf + 32];
    }
#pragma unroll
    for (int s = 0; s < 16; s++) {
        const int cur = s & 1, nxt = cur ^ 1;
        if (s < 15) {
            int kf = kf0 + s + 1;
            int af = (kf * 2 + mf) * 32 + lane;
            ah[nxt] = Aph[af];
            int wf = (kf * 2) * 32 + lane;
            bh[nxt][0] = Wh[wf]; bh[nxt][1] = Wh[wf + 32];
            bl[nxt][0] = Wl[wf]; bl[nxt][1] = Wl[wf + 32];
        }
#pragma unroll
        for (int nf = 0; nf < 2; nf++) {
            mma16816(c[nf], &ah[cur].x, &bh[cur][nf].x);
            mma16816(c[nf], &ah[cur].x, &bl[cur][nf].x);
        }
    }
    const int r = lane >> 2, c2 = (lane & 3) * 2;
#pragma unroll
    for (int nf = 0; nf < 2; nf++) {
        int off = kg * 640 + (mf * 16 + r) * 20 + nf * 8 + c2;
        *(float2*)(scr + off) = make_float2(c[nf][0], c[nf][1]);
        *(float2*)(scr + off + 8 * 20) = make_float2(c[nf][2], c[nf][3]);
    }
}

// pack sbuf[32][20] (16 cols) into 2 A-frags (hi+lo) at kf = jkf (warps 0-1)
__device__ __forceinline__ void pack2(const float* __restrict__ sbuf,
                                      uint4* __restrict__ dsth,
                                      uint4* __restrict__ dstl,
                                      int jkf, int wid, int lane)
{
    if (wid < 2) {
        const int mf = wid;
        const int r = lane >> 2, c2 = (lane & 3) * 2;
        const float* p = sbuf + (mf * 16 + r) * 20 + c2;
        uint32_t h0, h1, h2, h3, l0, l1, l2, l3;
        splitp(p[0], p[1], h0, l0);
        splitp(p[160], p[161], h1, l1);
        splitp(p[8], p[9], h2, l2);
        splitp(p[168], p[169], h3, l3);
        const int fi = (jkf * 2 + mf) * 32 + lane;
        dsth[fi] = make_uint4(h0, h1, h2, h3);
        dstl[fi] = make_uint4(l0, l1, l2, l3);
    }
}

// hi-only pack (for rh)
__device__ __forceinline__ void pack2h(const float* __restrict__ sbuf,
                                       uint4* __restrict__ dsth,
                                       int jkf, int wid, int lane)
{
    if (wid < 2) {
        const int mf = wid;
        const int r = lane >> 2, c2 = (lane & 3) * 2;
        const float* p = sbuf + (mf * 16 + r) * 20 + c2;
        uint32_t h0 = bfpack(p[0], p[1]);
        uint32_t h1 = bfpack(p[160], p[161]);
        uint32_t h2 = bfpack(p[8], p[9]);
        uint32_t h3 = bfpack(p[168], p[169]);
        dsth[(jkf * 2 + mf) * 32 + lane] = make_uint4(h0, h1, h2, h3);
    }
}

__global__ void __launch_bounds__(256, 1) gru_step_kernel(
    const float* __restrict__ h0in,
    const float* __restrict__ Whz, const float* __restrict__ Whr,
    const float* __restrict__ Whh,
    const float* __restrict__ Whz_b, const float* __restrict__ Whr_b,
    const float* __restrict__ Whh_b,
    const float* __restrict__ Wiz_b, const float* __restrict__ Wir_b,
    const float* __restrict__ Wih_b,
    const void* __restrict__ lengths,
    float* __restrict__ out, int write_last)
{
    extern __shared__ char sm[];
    uint2* Wzh = (uint2*)(sm + W_ZH);
    uint2* Wzl = (uint2*)(sm + W_ZL);
    uint2* Wrh = (uint2*)(sm + W_RH);
    uint2* Wrl = (uint2*)(sm + W_RL);
    uint2* Wch = (uint2*)(sm + W_CH);
    uint2* Wcl = (uint2*)(sm + W_CL);
    float* scrz = (float*)(sm + PB_SCRZ);
    float* scrr = (float*)(sm + PB_SCRR);
    float* sbuf = (float*)(sm + PB_SBUF);
    float* bia = (float*)(sm + PB_BIA);     // [0:16) z, [16:32) r, [32:48) c
    int* slen = (int*)(sm + PB_SLEN);

    const int tid = threadIdx.x, wid = tid >> 5, lane = tid & 31;
    const int b = blockIdx.x;
    const int half = b >> 6;
    const int j = b & 63;
    const int gn0 = j * 16;
    const int row0 = half * 32;

    packW(Whz, gn0, Wzh, Wzl, tid);
    packW(Whr, gn0, Wrh, Wrl, tid);
    packW(Whh, gn0, Wch, Wcl, tid);
    if (tid < 16) {
        bia[tid]      = Whz_b[gn0 + tid] + Wiz_b[gn0 + tid];
        bia[16 + tid] = Whr_b[gn0 + tid] + Wir_b[gn0 + tid];
        bia[32 + tid] = Whh_b[gn0 + tid] + Wih_b[gn0 + tid];
    }
    {   // lengths dtype auto-detect (int64 -> high word of elem0 is 0)
        const int* L32 = (const int*)lengths;
        int is64 = (L32[1] == 0);
        if (tid < 32) {
            int rr = row0 + tid;
            slen[tid] = is64 ? (int)((const long long*)lengths)[rr] : L32[rr];
        }
    }

    const int m = tid >> 3;          // 0..31
    const int nq = (tid & 7) * 2;    // 0..14
    const size_t xrow = (size_t)(row0 + m) * NH + gn0 + nq;
    float h0r, h1r;                  // local h tile (2 elems/thread)

    {   // init h
        float2 v = *(const float2*)(h0in + xrow);
        h0r = v.x; h1r = v.y;
        *(float2*)(sbuf + m * 20 + nq) = v;
        __syncthreads();
        pack2(sbuf, g_hhf[0][half], g_hlf[0][half], j, wid, lane);
        __syncthreads();
        if (tid == 0) { __threadfence(); st_rel(&g_fh[half * 64 + j], 0); }
    }

    const int sl = slen[m];
    const size_t GATE = (size_t)TSTEPS * BATCH * NH;
    const float* Xz = g_X + xrow;
    const float* Xr = g_X + GATE + xrow;
    const float* Xh = g_X + 2 * GATE + xrow;
    const int* fhb = g_fh + half * 64;
    const int* frhb = g_frh + half * 64;
    const uint4* hhfp[2] = {g_hhf[0][half], g_hhf[1][half]};
    const uint4* hlfp[2] = {g_hlf[0][half], g_hlf[1][half]};
    uint4* rhh = g_rhhf[half];

    for (int t = 0; t < TSTEPS; t++) {
        float2 xz = *(const float2*)(Xz + (size_t)t * BATCH * NH);
        float2 xr = *(const float2*)(Xr + (size_t)t * BATCH * NH);
        float2 xh = *(const float2*)(Xh + (size_t)t * BATCH * NH);
        // ---- fused z+r gemm ----
        block_wait64(fhb, t);
        gemm_zr(hhfp[t & 1], hlfp[t & 1], Wzh, Wzl, Wrh, Wrl, scrz, scrr, wid, lane);
        __syncthreads();
        // ---- epi1: z (registers), rh -> sbuf ----
        float z0 = bia[nq] + xz.x, z1 = bia[nq + 1] + xz.y;
        float r0 = bia[16 + nq] + xr.x, r1 = bia[16 + nq + 1] + xr.y;
#pragma unroll
        for (int kg = 0; kg < 4; kg++) {
            float2 az = *(const float2*)(scrz + kg * 640 + m * 20 + nq);
            float2 ar = *(const float2*)(scrr + kg * 640 + m * 20 + nq);
            z0 += az.x; z1 += az.y;
            r0 += ar.x; r1 += ar.y;
        }
        z0 = 1.0f / (1.0f + expf(-z0));
        z1 = 1.0f / (1.0f + expf(-z1));
        r0 = 1.0f / (1.0f + expf(-r0));
        r1 = 1.0f / (1.0f + expf(-r1));
        *(float2*)(sbuf + m * 20 + nq) = make_float2(r0 * h0r, r1 * h1r);
        __syncthreads();
        pack2h(sbuf, rhh, j, wid, lane);
        __syncthreads();
        if (tid == 0) { __threadfence(); st_rel(&g_frh[half * 64 + j], t + 1); }
        // ---- candidate gemm (2-term, hi plane only) ----
        block_wait64(frhb, t + 1);
        gemm_c(rhh, Wch, Wcl, scrz, wid, lane);
        __syncthreads();
        // ---- epi2: update h ----
        float p0 = bia[32 + nq] + xh.x, p1 = bia[32 + nq + 1] + xh.y;
#pragma unroll
        for (int kg = 0; kg < 4; kg++) {
            float2 a = *(const float2*)(scrz + kg * 640 + m * 20 + nq);
            p0 += a.x; p1 += a.y;
        }
        float hn0 = (1.0f - z0) * h0r + z0 * tanhf(p0);
        float hn1 = (1.0f - z1) * h1r + z1 * tanhf(p1);
        if (t >= sl) { hn0 = h0r; hn1 = h1r; }
        h0r = hn0; h1r = hn1;
        *(float2*)(out + (size_t)t * BATCH * NH + xrow) = make_float2(hn0, hn1);
        *(float2*)(sbuf + m * 20 + nq) = make_float2(hn0, hn1);
        __syncthreads();
        pack2(sbuf, g_hhf[(t + 1) & 1][half], g_hlf[(t + 1) & 1][half], j, wid, lane);
        __syncthreads();
        if (tid == 0) { __threadfence(); st_rel(&g_fh[half * 64 + j], t + 1); }
    }
    if (write_last) {
        *(float2*)(out + (size_t)TSTEPS * BATCH * NH + xrow) = make_float2(h0r, h1r);
    }
}

// ============================= launch =======================================
extern "C" void kernel_launch(void* const* d_in, const int* in_sizes, int n_in,
                              void* d_out, int out_size)
{
    const float* input = (const float*)d_in[0];
    const float* h0    = (const float*)d_in[1];
    const float* Wiz_w = (const float*)d_in[2];
    const float* Wiz_b = (const float*)d_in[3];
    const float* Wir_w = (const float*)d_in[4];
    const float* Wir_b = (const float*)d_in[5];
    const float* Wih_w = (const float*)d_in[6];
    const float* Wih_b = (const float*)d_in[7];
    const float* Whz_w = (const float*)d_in[8];
    const float* Whz_b = (const float*)d_in[9];
    const float* Whr_w = (const float*)d_in[10];
    const float* Whr_b = (const float*)d_in[11];
    const float* Whh_w = (const float*)d_in[12];
    const float* Whh_b = (const float*)d_in[13];
    const void*  lengths = d_in[14];

    cudaFuncSetAttribute(input_proj_kernel,
                         cudaFuncAttributeMaxDynamicSharedMemorySize, PA_SMEM);
    cudaFuncSetAttribute(gru_step_kernel,
                         cudaFuncAttributeMaxDynamicSharedMemorySize, PB_SMEM);

    init_misc_kernel<<<1, 128>>>();
    input_proj_kernel<<<256 * 24, 256, PA_SMEM>>>(input, Wiz_w, Wir_w, Wih_w);

    int write_last = (out_size >= TSTEPS * BATCH * NH + BATCH * NH) ? 1 : 0;
    gru_step_kernel<<<NBLK, 256, PB_SMEM>>>(
        h0, Whz_w, Whr_w, Whh_w, Whz_b, Whr_b, Whh_b,
        Wiz_b, Wir_b, Wih_b, lengths, (float*)d_out, write_last);
}